// round 8
// baseline (speedup 1.0000x reference)
#include <cuda_runtime.h>
#include <cstdint>

#define D_IN 256
#define D_OUT 128
#define SEGSZ 64
#define N_SEQ 2048
#define ROWS 128            // 2 segments per CTA
#define N_CTA (N_SEQ / 2)   // 1024

namespace {
constexpr int H_ST = D_OUT + 4;   // 132: conflict-free A-frag / ctx B-frag loads
constexpr int X_ST = 32 + 4;      // 36: 32-col k-chunks, 16B-aligned rows (144B)
constexpr int S_ST = 64 + 4;      // 68

constexpr int OFF_H = 0;
constexpr int OFF_X = OFF_H + ROWS * H_ST;    // 16896 floats (67584 B, 16B aligned)
constexpr int XBUF  = ROWS * X_ST;            // 4608 floats per stage
constexpr int OFF_S = OFF_X;                  // Ss (128*68=8704) overlays both X stages (9216)
constexpr int OFF_B = OFF_X + 2 * XBUF;       // 26112
constexpr int SMEM_FLOATS = OFF_B + D_OUT;    // 26240
constexpr int SMEM_BYTES  = SMEM_FLOATS * 4;  // 104960 B; x2 CTAs = 209920 <= 228KB/SM
} // namespace

// W in MMA B-fragment layout, tf32-rounded:
// g_wfrag[(k8*16 + ng)*32 + lane] = { W[k8*8 + (lane&3)][ng*8 + (lane>>2)],
//                                     W[k8*8 + (lane&3) + 4][ng*8 + (lane>>2)] }
__device__ float2 g_wfrag[32 * 16 * 32];

__device__ __forceinline__ float tf32r(float x) {
    uint32_t u = __float_as_uint(x);
    asm("cvt.rna.tf32.f32 %0, %1;" : "=r"(u) : "r"(u));
    return __uint_as_float(u);
}

__device__ __forceinline__ uint32_t tf32u(float x) {
    uint32_t u = __float_as_uint(x);
    asm("cvt.rna.tf32.f32 %0, %1;" : "=r"(u) : "r"(u));
    return u;
}

__device__ __forceinline__ void mma8(float* d, const uint32_t* a, const uint32_t* b) {
    asm volatile(
        "mma.sync.aligned.m16n8k8.row.col.f32.tf32.tf32.f32 "
        "{%0,%1,%2,%3}, {%4,%5,%6,%7}, {%8,%9}, {%0,%1,%2,%3};\n"
        : "+f"(d[0]), "+f"(d[1]), "+f"(d[2]), "+f"(d[3])
        : "r"(a[0]), "r"(a[1]), "r"(a[2]), "r"(a[3]), "r"(b[0]), "r"(b[1]));
}

__device__ __forceinline__ void cp_async16(uint32_t dst_smem, const void* src) {
    asm volatile("cp.async.cg.shared.global [%0], [%1], 16;\n"
                 :: "r"(dst_smem), "l"(src) : "memory");
}

__global__ __launch_bounds__(256)
void prep_w_kernel(const float* __restrict__ Wg) {
    int i = blockIdx.x * 256 + threadIdx.x;   // 0..16383
    int k8i = i >> 9;
    int ng  = (i >> 5) & 15;
    int ln  = i & 31;
    int row = k8i * 8 + (ln & 3);
    int col = ng * 8 + (ln >> 2);
    g_wfrag[i] = make_float2(tf32r(Wg[row * D_OUT + col]),
                             tf32r(Wg[(row + 4) * D_OUT + col]));
}

__global__ __launch_bounds__(256, 2)
void attn_hidden_kernel(const float* __restrict__ Xall,
                        const float* __restrict__ bg,
                        float* __restrict__ out)
{
    extern __shared__ float smem[];
    float* hs = smem + OFF_H;
    float* Ss = smem + OFF_S;    // 128 x 68, overlays X stages
    float* bs = smem + OFF_B;

    const int tid  = threadIdx.x;
    const int warp = tid >> 5;
    const int lane = tid & 31;
    const int lr   = lane >> 2;
    const int lc   = lane & 3;

    // GEMM warp layout: seg = warp&1 (which 64-row segment), nq = warp>>1 (32-col strip)
    const int seg  = warp & 1;
    const int nq   = warp >> 1;          // 0..3
    const int n0   = nq * 32;
    const int rowb = seg * SEGSZ;
    // per-segment 4-warp layout for S/ctx phases
    const int wq   = warp >> 1;          // 0..3 within segment
    const int ms   = (wq & 1) * 32;      // S: 32-row strip
    const int ns   = (wq >> 1) * 32;     // S: 32-col strip
    const int mc   = (wq & 1) * 32;      // ctx: 32-row strip
    const int nc   = (wq >> 1) * 64;     // ctx: 64-col strip

    const int g2 = blockIdx.x;
    const float* Xg = Xall + (size_t)g2 * ROWS * D_IN;

    if (tid < D_OUT) bs[tid] = bg[tid];

    const uint32_t xs_s0 = (uint32_t)__cvta_generic_to_shared(smem + OFF_X);

    // issue X chunk 0 (128 rows x 32 cols, 4x16B per thread)
    #pragma unroll
    for (int t = 0; t < 4; ++t) {
        int j = tid + t * 256;           // 0..1023 float4s
        int row = j >> 3, q = j & 7;
        cp_async16(xs_s0 + (row * X_ST + q * 4) * 4, Xg + row * D_IN + q * 4);
    }
    asm volatile("cp.async.commit_group;\n" ::: "memory");

    // ================= GEMM: h = X(128x256) @ W(256x128) =================
    float acc[4][4][4];
    #pragma unroll
    for (int mt = 0; mt < 4; ++mt)
        #pragma unroll
        for (int nt = 0; nt < 4; ++nt)
            #pragma unroll
            for (int i = 0; i < 4; ++i) acc[mt][nt][i] = 0.f;

    // register double-buffer of W B-fragments (W lives in L2)
    uint32_t bfr[2][4][2];
    #pragma unroll
    for (int nt = 0; nt < 4; ++nt) {
        float2 w2 = __ldg(&g_wfrag[(nq * 4 + nt) * 32 + lane]);   // k8g = 0
        bfr[0][nt][0] = __float_as_uint(w2.x);
        bfr[0][nt][1] = __float_as_uint(w2.y);
    }

    for (int kc = 0; kc < 8; ++kc) {
        __syncthreads();   // all warps done with buffer (kc+1)&1 (used in chunk kc-1)
        if (kc < 7) {
            const uint32_t dst = xs_s0 + ((kc + 1) & 1) * (XBUF * 4);
            #pragma unroll
            for (int t = 0; t < 4; ++t) {
                int j = tid + t * 256;
                int row = j >> 3, q = j & 7;
                cp_async16(dst + (row * X_ST + q * 4) * 4,
                           Xg + row * D_IN + (kc + 1) * 32 + q * 4);
            }
            asm volatile("cp.async.commit_group;\n" ::: "memory");
            asm volatile("cp.async.wait_group 1;\n" ::: "memory");
        } else {
            asm volatile("cp.async.wait_group 0;\n" ::: "memory");
        }
        __syncthreads();   // chunk kc visible to all warps

        const float* Xs = smem + OFF_X + (kc & 1) * XBUF;
        #pragma unroll
        for (int k8 = 0; k8 < 4; ++k8) {
            const int k8g = kc * 4 + k8;
            const int cur = k8g & 1;
            const int nk  = (k8g < 31) ? k8g + 1 : 31;   // prefetch next B frags
            #pragma unroll
            for (int nt = 0; nt < 4; ++nt) {
                float2 w2 = __ldg(&g_wfrag[(nk * 16 + nq * 4 + nt) * 32 + lane]);
                bfr[cur ^ 1][nt][0] = __float_as_uint(w2.x);
                bfr[cur ^ 1][nt][1] = __float_as_uint(w2.y);
            }
            const int kl = k8 * 8;
            uint32_t af[4][4];
            #pragma unroll
            for (int mt = 0; mt < 4; ++mt) {
                const float* p = Xs + (rowb + mt * 16 + lr) * X_ST + kl + lc;
                af[mt][0] = tf32u(p[0]);
                af[mt][1] = tf32u(p[8 * X_ST]);
                af[mt][2] = tf32u(p[4]);
                af[mt][3] = tf32u(p[8 * X_ST + 4]);
            }
            #pragma unroll
            for (int mt = 0; mt < 4; ++mt)
                #pragma unroll
                for (int nt = 0; nt < 4; ++nt)
                    mma8(acc[mt][nt], af[mt], bfr[cur][nt]);
        }
    }

    // epilogue: h (+bias), tf32-rounded -> smem
    #pragma unroll
    for (int mt = 0; mt < 4; ++mt) {
        #pragma unroll
        for (int nt = 0; nt < 4; ++nt) {
            int row = rowb + mt * 16 + lr;
            int col = n0 + nt * 8 + 2 * lc;
            hs[row * H_ST + col]           = tf32r(acc[mt][nt][0] + bs[col]);
            hs[row * H_ST + col + 1]       = tf32r(acc[mt][nt][1] + bs[col + 1]);
            hs[(row + 8) * H_ST + col]     = tf32r(acc[mt][nt][2] + bs[col]);
            hs[(row + 8) * H_ST + col + 1] = tf32r(acc[mt][nt][3] + bs[col + 1]);
        }
    }
    __syncthreads();

    // ================= S = h_seg @ h_seg^T  (64x64, K=128) per segment =================
    float accS[2][4][4];
    #pragma unroll
    for (int mt = 0; mt < 2; ++mt)
        #pragma unroll
        for (int nt = 0; nt < 4; ++nt)
            #pragma unroll
            for (int i = 0; i < 4; ++i) accS[mt][nt][i] = 0.f;

    #pragma unroll
    for (int k8 = 0; k8 < 16; ++k8) {
        const int kl = k8 * 8;
        uint32_t af[2][4];
        #pragma unroll
        for (int mt = 0; mt < 2; ++mt) {
            const float* p = hs + (rowb + ms + mt * 16 + lr) * H_ST + kl + lc;
            af[mt][0] = __float_as_uint(p[0]);
            af[mt][1] = __float_as_uint(p[8 * H_ST]);
            af[mt][2] = __float_as_uint(p[4]);
            af[mt][3] = __float_as_uint(p[8 * H_ST + 4]);
        }
        uint32_t bf[4][2];
        #pragma unroll
        for (int nt = 0; nt < 4; ++nt) {
            const float* p = hs + (rowb + ns + nt * 8 + lr) * H_ST + kl + lc;
            bf[nt][0] = __float_as_uint(p[0]);
            bf[nt][1] = __float_as_uint(p[4]);
        }
        #pragma unroll
        for (int mt = 0; mt < 2; ++mt)
            #pragma unroll
            for (int nt = 0; nt < 4; ++nt)
                mma8(accS[mt][nt], af[mt], bf[nt]);
    }
    // store S raw fp32 (Ss overlays X stages; all warps are past the GEMM)
    #pragma unroll
    for (int mt = 0; mt < 2; ++mt) {
        #pragma unroll
        for (int nt = 0; nt < 4; ++nt) {
            int row = rowb + ms + mt * 16 + lr;
            int col = ns + nt * 8 + 2 * lc;
            Ss[row * S_ST + col]           = accS[mt][nt][0];
            Ss[row * S_ST + col + 1]       = accS[mt][nt][1];
            Ss[(row + 8) * S_ST + col]     = accS[mt][nt][2];
            Ss[(row + 8) * S_ST + col + 1] = accS[mt][nt][3];
        }
    }
    __syncthreads();

    // ================= softmax: 128 rows, 2 threads/row, in place, P tf32 =================
    {
        const int r  = tid >> 1;     // 0..127
        const int sq = tid & 1;      // half-row (32 cols)
        float4* rp = reinterpret_cast<float4*>(Ss + r * S_ST + sq * 32);
        float v[32];
        #pragma unroll
        for (int j = 0; j < 8; ++j) {
            float4 t = rp[j];
            v[4*j] = t.x; v[4*j+1] = t.y; v[4*j+2] = t.z; v[4*j+3] = t.w;
        }
        float m = v[0];
        #pragma unroll
        for (int i = 1; i < 32; ++i) m = fmaxf(m, v[i]);
        m = fmaxf(m, __shfl_xor_sync(0xffffffffu, m, 1));
        float s = 0.f;
        #pragma unroll
        for (int i = 0; i < 32; ++i) { v[i] = __expf(v[i] - m); s += v[i]; }
        s += __shfl_xor_sync(0xffffffffu, s, 1);
        const float inv = 1.0f / s;
        #pragma unroll
        for (int j = 0; j < 8; ++j) {
            rp[j] = make_float4(tf32r(v[4*j] * inv),   tf32r(v[4*j+1] * inv),
                                tf32r(v[4*j+2] * inv), tf32r(v[4*j+3] * inv));
        }
    }
    __syncthreads();

    // ================= ctx = P(64x64) @ h_seg(64x128) per segment =================
    float accC[2][8][4];
    #pragma unroll
    for (int mt = 0; mt < 2; ++mt)
        #pragma unroll
        for (int nt = 0; nt < 8; ++nt)
            #pragma unroll
            for (int i = 0; i < 4; ++i) accC[mt][nt][i] = 0.f;

    #pragma unroll
    for (int k8 = 0; k8 < 8; ++k8) {
        const int kl = k8 * 8;
        uint32_t af[2][4];
        #pragma unroll
        for (int mt = 0; mt < 2; ++mt) {
            const float* p = Ss + (rowb + mc + mt * 16 + lr) * S_ST + kl + lc;
            af[mt][0] = __float_as_uint(p[0]);
            af[mt][1] = __float_as_uint(p[8 * S_ST]);
            af[mt][2] = __float_as_uint(p[4]);
            af[mt][3] = __float_as_uint(p[8 * S_ST + 4]);
        }
        uint32_t bf[8][2];
        #pragma unroll
        for (int nt = 0; nt < 8; ++nt) {
            const float* p = hs + (rowb + kl + lc) * H_ST + nc + nt * 8 + lr;
            bf[nt][0] = __float_as_uint(p[0]);
            bf[nt][1] = __float_as_uint(p[4 * H_ST]);
        }
        #pragma unroll
        for (int mt = 0; mt < 2; ++mt)
            #pragma unroll
            for (int nt = 0; nt < 8; ++nt)
                mma8(accC[mt][nt], af[mt], bf[nt]);
    }

    // store ctx to gmem
    #pragma unroll
    for (int mt = 0; mt < 2; ++mt) {
        #pragma unroll
        for (int nt = 0; nt < 8; ++nt) {
            size_t row = (size_t)g2 * ROWS + rowb + mc + mt * 16 + lr;
            int col = nc + nt * 8 + 2 * lc;
            *reinterpret_cast<float2*>(out + row * D_OUT + col) =
                make_float2(accC[mt][nt][0], accC[mt][nt][1]);
            *reinterpret_cast<float2*>(out + (row + 8) * D_OUT + col) =
                make_float2(accC[mt][nt][2], accC[mt][nt][3]);
        }
    }
}

extern "C" void kernel_launch(void* const* d_in, const int* in_sizes, int n_in,
                              void* d_out, int out_size) {
    (void)in_sizes; (void)n_in; (void)out_size;
    const float* X = (const float*)d_in[0];
    const float* W = (const float*)d_in[1];
    const float* b = (const float*)d_in[2];
    float* out = (float*)d_out;

    prep_w_kernel<<<64, 256>>>(W);   // 16384 fragment float2s

    cudaFuncSetAttribute(attn_hidden_kernel,
                         cudaFuncAttributeMaxDynamicSharedMemorySize, SMEM_BYTES);
    attn_hidden_kernel<<<N_CTA, 256, SMEM_BYTES>>>(X, b, out);
}